// round 15
// baseline (speedup 1.0000x reference)
#include <cuda_runtime.h>
#include <math.h>

// Chamfer loss, B=4, C=3, Np=Ng=8192. R15 = R11 champion shape (256 blocks,
// 2/SM, single wave) with per-stage overhead halved:
//  - TGQ=256 -> 32 stages: half the barriers, half the loop overhead, and the
//    column reduce uses ALL 256 threads (1 col each) instead of half idle.
//  - zero-divergence prefetch (every thread stages exactly 1 gt point).
//  - rows flushed via complement atomicMax (no per-block sred reduction).
//  - single launch: zero-init == FLT_MAX via complement encoding; last block
//    (ticket) runs the vectorized finalize and resets globals for replay.

#define BATCH   4
#define NPT     8192
#define TPQ     128                      // predict points per block
#define TGQ     256                      // gt points per stage
#define NSTAGES (NPT / TGQ)              // 32
#define NTH     256                      // 16 (g=tx) x 16 (p=ty)
#define NBLOCKS (BATCH * (NPT / TPQ))    // 256
#define EPSF    1e-12f

// [0, B*N): col mins (complement bits),  [B*N, 2*B*N): row mins
__device__ unsigned int g_minbuf[2 * BATCH * NPT];
__device__ unsigned int g_done;

__global__ __launch_bounds__(NTH, 2)
void chamfer_main(const float* __restrict__ P, const float* __restrict__ G,
                  float* __restrict__ out) {
    const int b     = blockIdx.y;
    const int pbase = blockIdx.x * TPQ;
    const float* Pb = P + (size_t)b * 3 * NPT;
    const float* Gb = G + (size_t)b * 3 * NPT;
    const int tid = threadIdx.x;
    const int tx  = tid & 15;        // g direction
    const int ty  = tid >> 4;        // p direction

    __shared__ float4 sp[TPQ];
    __shared__ float4 sg[2][TGQ];               // double buffer
    __shared__ float  cbuf[2][16][TGQ + 1];     // double buffer, padded
    __shared__ float  sred[NTH];
    __shared__ unsigned int ticket;

    // ---- prologue: prefetch stage-0 gt (1 pt/thread), p tile ----
    float rx = Gb[tid];
    float ry = Gb[NPT + tid];
    float rz = Gb[2 * NPT + tid];
    if (tid < TPQ) {
        float px = Pb[pbase + tid];
        float py = Pb[NPT + pbase + tid];
        float pz = Pb[2 * NPT + pbase + tid];
        sp[tid] = make_float4(-2.f * px, -2.f * py, -2.f * pz,
                              px * px + py * py + pz * pz);
    }
    sg[0][tid] = make_float4(rx, ry, rz, rx * rx + ry * ry + rz * rz);
    __syncthreads();

    float pa[8], pb_[8], pc[8], pp2[8], rowmin[8];
#pragma unroll
    for (int ii = 0; ii < 8; ii++) {
        float4 v = sp[ty * 8 + ii];
        pa[ii] = v.x; pb_[ii] = v.y; pc[ii] = v.z; pp2[ii] = v.w;
        rowmin[ii] = 3.4e38f;
    }

    for (int s = 0; s < NSTAGES; s++) {
        const int cur = s & 1, nxt = cur ^ 1;

        // issue next-stage gmem loads now; latency hidden under compute
        if (s + 1 < NSTAGES) {
            int g = (s + 1) * TGQ + tid;
            rx = Gb[g]; ry = Gb[NPT + g]; rz = Gb[2 * NPT + g];
        }

        // four g-passes of 64 columns each (RG=4 keeps regs ~80)
#pragma unroll
        for (int h = 0; h < 4; h++) {
            float gx[4], gy[4], gz[4], g2[4], colmin[4];
#pragma unroll
            for (int jj = 0; jj < 4; jj++) {
                float4 v = sg[cur][h * 64 + jj * 16 + tx];
                gx[jj] = v.x; gy[jj] = v.y; gz[jj] = v.z; g2[jj] = v.w;
                colmin[jj] = 3.4e38f;
            }

#pragma unroll
            for (int ii = 0; ii < 8; ii++) {
#pragma unroll
                for (int jj = 0; jj < 4; jj++) {
                    float e = fmaf(pc[ii], gz[jj], g2[jj]);
                    e = fmaf(pb_[ii], gy[jj], e);
                    e = fmaf(pa[ii], gx[jj], e);
                    rowmin[ii] = fminf(rowmin[ii], e);
                    colmin[jj] = fminf(colmin[jj], e + pp2[ii]);
                }
            }

            // per-warp column partials (pre-barrier stores)
#pragma unroll
            for (int jj = 0; jj < 4; jj++)
                cbuf[cur][ty][h * 64 + jj * 16 + tx] = colmin[jj];
        }

        // stage s+1 gt chunk -> other smem buffer (prefetch regs landed)
        if (s + 1 < NSTAGES)
            sg[nxt][tid] = make_float4(rx, ry, rz, rx * rx + ry * ry + rz * rz);

        __syncthreads();   // the ONLY barrier per stage

        // column reduce: ALL 256 threads, one g column each; overlaps next
        // stage's compute in other warps (cbuf is double-buffered)
        {
            float v[16];
#pragma unroll
            for (int t = 0; t < 16; t++) v[t] = cbuf[cur][t][tid];
#pragma unroll
            for (int st = 8; st > 0; st >>= 1)
#pragma unroll
                for (int t = 0; t < 8; t++)
                    if (t < st) v[t] = fminf(v[t], v[t + st]);
            float m = fmaxf(v[0], EPSF);   // clamp (ref); positive bits
            atomicMax(&g_minbuf[b * NPT + s * TGQ + tid],
                      0x7f7fffffu - (unsigned int)__float_as_int(m));
        }
    }

    // row-min reduce across tx (intra-warp, once), then flush via atomicMax
#pragma unroll
    for (int ii = 0; ii < 8; ii++) {
        float m = rowmin[ii];
#pragma unroll
        for (int off = 1; off < 16; off <<= 1)
            m = fminf(m, __shfl_xor_sync(0xffffffffu, m, off));
        if (tx == 0) {
            m = fmaxf(m + pp2[ii], EPSF);
            atomicMax(&g_minbuf[BATCH * NPT + b * NPT + pbase + ty * 8 + ii],
                      0x7f7fffffu - (unsigned int)__float_as_int(m));
        }
    }

    // ---- single-launch epilogue ----
    __threadfence();        // every thread: its atomics reach L2 before ticket
    __syncthreads();
    if (tid == 0)
        ticket = atomicAdd(&g_done, 1u);
    __syncthreads();

    if (ticket == NBLOCKS - 1) {
        // all blocks done (their fences precede the ticket). Vectorized
        // gather over col+row mins (16k uint4) + reset for graph replay.
        uint4* m4 = reinterpret_cast<uint4*>(g_minbuf);
        const uint4 z4 = make_uint4(0u, 0u, 0u, 0u);
        float s = 0.f;
#pragma unroll 4
        for (int i = tid; i < (2 * BATCH * NPT) / 4; i += NTH) {
            uint4 c = __ldcg(&m4[i]);
            s += sqrtf(__int_as_float((int)(0x7f7fffffu - c.x)));
            s += sqrtf(__int_as_float((int)(0x7f7fffffu - c.y)));
            s += sqrtf(__int_as_float((int)(0x7f7fffffu - c.z)));
            s += sqrtf(__int_as_float((int)(0x7f7fffffu - c.w)));
            m4[i] = z4;                                          // reset
        }
        sred[tid] = s;
        __syncthreads();
        for (int st = NTH / 2; st > 0; st >>= 1) {
            if (tid < st) sred[tid] += sred[tid + st];
            __syncthreads();
        }
        if (tid == 0) {
            out[0] = sred[0] / (float)(BATCH * 2 * NPT);   // denom = B*(Np+Ng)
            g_done = 0u;                                   // reset
        }
    }
}

extern "C" void kernel_launch(void* const* d_in, const int* in_sizes, int n_in,
                              void* d_out, int out_size) {
    const float* P = (const float*)d_in[0];
    const float* G = (const float*)d_in[1];

    dim3 grid(NPT / TPQ, BATCH);             // 64 x 4 = 256 blocks, ONE launch
    chamfer_main<<<grid, NTH>>>(P, G, (float*)d_out);
}

// round 16
// speedup vs baseline: 1.2277x; 1.2277x over previous
#include <cuda_runtime.h>
#include <math.h>

// Chamfer loss, B=4, C=3, Np=Ng=8192. R16 = R11 champion core, VERBATIM hot
// loop, with a hierarchical finalize:
//  - per-batch ticket: the last of each batch's 64 blocks finalizes that
//    batch's 8192 column mins (overlapped with other batches' compute),
//  - global ticket (4 arrivals) writes out and resets all state for replay.
//  Evidence: R7 ran this exact core at 77.0us; R11's +11.8us was the
//  serialized single-block finalize tail. R12-R15 structural changes all
//  grew total issued slots -> rejected.
//  - col mins complement-encoded (atomicMax of 0x7f7fffff - bits): zero-init
//    == FLT_MAX, no init kernel, order-independent => deterministic.
//  - all sums in one fixed-point u64 accumulator (integer adds commute).

#define BATCH   4
#define NPT     8192
#define TPQ     128                      // predict points per block
#define TGQ     128                      // gt points per stage
#define NSTAGES (NPT / TGQ)              // 64
#define NTH     256                      // 16 (g=tx) x 16 (p=ty)
#define NBLK_B  (NPT / TPQ)              // 64 blocks per batch
#define EPSF    1e-12f
#define FPSCALE 4294967296.0             // 2^32 fixed point

__device__ unsigned int       g_colmax[BATCH * NPT];   // complement bits (0 = FLT_MAX)
__device__ unsigned long long g_acc;                   // fixed-point total (rows + cols)
__device__ unsigned int       g_done_b[BATCH];         // per-batch completion counters
__device__ unsigned int       g_done_all;              // batch-finalizer counter

__global__ __launch_bounds__(NTH, 3)
void chamfer_main(const float* __restrict__ P, const float* __restrict__ G,
                  float* __restrict__ out) {
    const int b     = blockIdx.y;
    const int pbase = blockIdx.x * TPQ;
    const float* Pb = P + (size_t)b * 3 * NPT;
    const float* Gb = G + (size_t)b * 3 * NPT;
    const int tid = threadIdx.x;
    const int tx  = tid & 15;        // g direction
    const int ty  = tid >> 4;        // p direction

    __shared__ float4 sp[TPQ];
    __shared__ float4 sg[2][TGQ];               // double buffer
    __shared__ float  cbuf[2][16][TGQ + 1];     // double buffer, padded
    __shared__ float  sred[NTH];
    __shared__ unsigned int ticket;

    // ---- prologue: prefetch stage-0 gt, load & transform p tile ----
    float rx = 0.f, ry = 0.f, rz = 0.f;
    if (tid < TGQ) {
        rx = Gb[tid];
        ry = Gb[NPT + tid];
        rz = Gb[2 * NPT + tid];
    }
    if (tid < TPQ) {
        float px = Pb[pbase + tid];
        float py = Pb[NPT + pbase + tid];
        float pz = Pb[2 * NPT + pbase + tid];
        sp[tid] = make_float4(-2.f * px, -2.f * py, -2.f * pz,
                              px * px + py * py + pz * pz);
    }
    if (tid < TGQ)
        sg[0][tid] = make_float4(rx, ry, rz, rx * rx + ry * ry + rz * rz);
    __syncthreads();

    float pa[8], pb_[8], pc[8], pp2[8], rowmin[8];
#pragma unroll
    for (int ii = 0; ii < 8; ii++) {
        float4 v = sp[ty * 8 + ii];
        pa[ii] = v.x; pb_[ii] = v.y; pc[ii] = v.z; pp2[ii] = v.w;
        rowmin[ii] = 3.4e38f;
    }

    for (int s = 0; s < NSTAGES; s++) {
        const int cur = s & 1, nxt = cur ^ 1;

        // issue next-stage gmem loads now; latency hidden under compute
        if (s + 1 < NSTAGES && tid < TGQ) {
            int g = (s + 1) * TGQ + tid;
            rx = Gb[g]; ry = Gb[NPT + g]; rz = Gb[2 * NPT + g];
        }

        // two g-passes of 64 columns each (RG=4) to keep registers small
#pragma unroll
        for (int h = 0; h < 2; h++) {
            float gx[4], gy[4], gz[4], g2[4], colmin[4];
#pragma unroll
            for (int jj = 0; jj < 4; jj++) {
                float4 v = sg[cur][h * 64 + jj * 16 + tx];
                gx[jj] = v.x; gy[jj] = v.y; gz[jj] = v.z; g2[jj] = v.w;
                colmin[jj] = 3.4e38f;
            }

#pragma unroll
            for (int ii = 0; ii < 8; ii++) {
#pragma unroll
                for (int jj = 0; jj < 4; jj++) {
                    float e = fmaf(pc[ii], gz[jj], g2[jj]);
                    e = fmaf(pb_[ii], gy[jj], e);
                    e = fmaf(pa[ii], gx[jj], e);
                    rowmin[ii] = fminf(rowmin[ii], e);
                    colmin[jj] = fminf(colmin[jj], e + pp2[ii]);
                }
            }

            // per-warp column partials (pre-barrier stores)
#pragma unroll
            for (int jj = 0; jj < 4; jj++)
                cbuf[cur][ty][h * 64 + jj * 16 + tx] = colmin[jj];
        }

        // stage s+1 gt chunk -> other smem buffer (prefetch regs landed)
        if (s + 1 < NSTAGES && tid < TGQ)
            sg[nxt][tid] = make_float4(rx, ry, rz, rx * rx + ry * ry + rz * rz);

        __syncthreads();   // the ONLY barrier per stage

        // column reduce overlaps next stage's compute in the other warps
        if (tid < TGQ) {
            float v[16];
#pragma unroll
            for (int t = 0; t < 16; t++) v[t] = cbuf[cur][t][tid];
#pragma unroll
            for (int st = 8; st > 0; st >>= 1)
#pragma unroll
                for (int t = 0; t < 8; t++)
                    if (t < st) v[t] = fminf(v[t], v[t + st]);
            float m = fmaxf(v[0], EPSF);   // clamp (ref); positive bits
            atomicMax(&g_colmax[b * NPT + s * TGQ + tid],
                      0x7f7fffffu - (unsigned int)__float_as_int(m));
        }
    }

    // row-min reduce across tx (intra-warp), sqrt, block-sum
#pragma unroll
    for (int ii = 0; ii < 8; ii++) {
        float m = rowmin[ii];
#pragma unroll
        for (int off = 1; off < 16; off <<= 1)
            m = fminf(m, __shfl_xor_sync(0xffffffffu, m, off));
        rowmin[ii] = m;
    }

    float rsum = 0.f;
    if (tx == 0) {
#pragma unroll
        for (int ii = 0; ii < 8; ii++)
            rsum += sqrtf(fmaxf(rowmin[ii] + pp2[ii], EPSF));
    }

    sred[tid] = rsum;
    __syncthreads();
    for (int st = NTH / 2; st > 0; st >>= 1) {
        if (tid < st) sred[tid] += sred[tid + st];
        __syncthreads();
    }
    if (tid == 0) {
        unsigned long long fx =
            (unsigned long long)((double)sred[0] * FPSCALE + 0.5);
        atomicAdd(&g_acc, fx);             // integer add: deterministic
    }

    // ---- hierarchical finalize ----
    __threadfence();        // each thread: its REDG atomics reach L2
    __syncthreads();        // block-wide: all fences done before the ticket
    if (tid == 0)
        ticket = atomicAdd(&g_done_b[b], 1u);
    __syncthreads();

    if (ticket == NBLK_B - 1) {
        // last block of THIS batch: finalize this batch's 8192 columns
        // (runs overlapped with other batches' compute). 2048 uint4 / 256 thr.
        uint4* cm4 = reinterpret_cast<uint4*>(g_colmax + (size_t)b * NPT);
        const uint4 z4 = make_uint4(0u, 0u, 0u, 0u);
        float s = 0.f;
#pragma unroll 2
        for (int i = tid; i < NPT / 4; i += NTH) {
            uint4 c = __ldcg(&cm4[i]);
            s += sqrtf(__int_as_float((int)(0x7f7fffffu - c.x)));
            s += sqrtf(__int_as_float((int)(0x7f7fffffu - c.y)));
            s += sqrtf(__int_as_float((int)(0x7f7fffffu - c.z)));
            s += sqrtf(__int_as_float((int)(0x7f7fffffu - c.w)));
            cm4[i] = z4;                                         // reset for replay
        }
        sred[tid] = s;
        __syncthreads();
        for (int st = NTH / 2; st > 0; st >>= 1) {
            if (tid < st) sred[tid] += sred[tid + st];
            __syncthreads();
        }
        if (tid == 0) {
            unsigned long long fx =
                (unsigned long long)((double)sred[0] * FPSCALE + 0.5);
            atomicAdd(&g_acc, fx);
            g_done_b[b] = 0u;              // reset this batch's counter
            __threadfence();
            unsigned int t2 = atomicAdd(&g_done_all, 1u);
            if (t2 == BATCH - 1) {
                unsigned long long tot = atomicAdd(&g_acc, 0ull);  // fenced-in reads
                out[0] = (float)((double)tot / FPSCALE
                                 / (double)(BATCH * 2 * NPT));     // denom = B*(Np+Ng)
                g_acc      = 0ull;         // reset
                g_done_all = 0u;           // reset
            }
        }
    }
}

extern "C" void kernel_launch(void* const* d_in, const int* in_sizes, int n_in,
                              void* d_out, int out_size) {
    const float* P = (const float*)d_in[0];
    const float* G = (const float*)d_in[1];

    dim3 grid(NPT / TPQ, BATCH);             // 64 x 4 = 256 blocks, ONE launch
    chamfer_main<<<grid, NTH>>>(P, G, (float*)d_out);
}